// round 15
// baseline (speedup 1.0000x reference)
#include <cuda_runtime.h>
#include <cuda_bf16.h>
#include <cstdint>

#define BB 2
#define HH 16
#define SS 2048
#define DD 64
#define SCL2E 0.1803368801111243f   /* (1/8) * log2(e) */
#define PADA 72
#define NQK ((size_t)BB * HH * SS * DD)
#define MROWB (SS / 8)              /* mask bits row stride: 256 bytes */
#define PLN64 (64 * PADA * 2)       /* 9216: one 64-row bf16 plane */
#define QPLN  (128 * PADA * 2)      /* 18432 */
/* smem: Qh|Ql | Kbuf0(h,l)|Kbuf1(h,l) | Vbuf0(h,l)|Vbuf1(h,l) */
#define KB_OFF (2 * QPLN)               /* 36864 */
#define VB_OFF (KB_OFF + 4 * PLN64)     /* 73728 */
#define FUSED_SMEM (VB_OFF + 4 * PLN64) /* 110592 */

__device__ int g_mask_flag;
__device__ __nv_bfloat16 g_qh[NQK], g_ql[NQK], g_kh[NQK], g_kl[NQK];
__device__ __nv_bfloat16 g_vh[NQK], g_vl[NQK];
__device__ unsigned long long g_maskbits[(size_t)BB * SS * SS / 64];

// ---------------------------------------------------------------------------
__global__ void probe_mask_kernel(const void* m) {
    uint4 w = ((const uint4*)m)[threadIdx.x];
    bool a01 = (w.x <= 1u) && (w.y <= 1u) && (w.z <= 1u) && (w.w <= 1u);
    auto okf = [](unsigned v) { return v == 0u || v == 0x3F800000u; };
    bool af = okf(w.x) && okf(w.y) && okf(w.z) && okf(w.w);
    int all1 = __syncthreads_and((int)a01);
    int all2 = __syncthreads_and((int)af);
    if (threadIdx.x == 0) g_mask_flag = all1 ? 0 : (all2 ? 1 : 2);
}

// ---------------------------------------------------------------------------
__device__ __forceinline__ uint32_t smem_u32(const void* p) {
    uint32_t a;
    asm("{ .reg .u64 t; cvta.to.shared.u64 t, %1; cvt.u32.u64 %0, t; }"
        : "=r"(a) : "l"(p));
    return a;
}

__device__ __forceinline__ void ldsm4(uint32_t* r, uint32_t addr) {
    asm volatile("ldmatrix.sync.aligned.m8n8.x4.shared.b16 {%0,%1,%2,%3}, [%4];"
                 : "=r"(r[0]), "=r"(r[1]), "=r"(r[2]), "=r"(r[3]) : "r"(addr));
}

__device__ __forceinline__ void ldsm4t(uint32_t* r, uint32_t addr) {
    asm volatile("ldmatrix.sync.aligned.m8n8.x4.trans.shared.b16 {%0,%1,%2,%3}, [%4];"
                 : "=r"(r[0]), "=r"(r[1]), "=r"(r[2]), "=r"(r[3]) : "r"(addr));
}

__device__ __forceinline__ void mma_bf16(float* c, const uint32_t* a,
                                         const uint32_t b0, const uint32_t b1) {
    asm volatile(
        "mma.sync.aligned.m16n8k16.row.col.f32.bf16.bf16.f32 "
        "{%0,%1,%2,%3}, {%4,%5,%6,%7}, {%8,%9}, {%0,%1,%2,%3};"
        : "+f"(c[0]), "+f"(c[1]), "+f"(c[2]), "+f"(c[3])
        : "r"(a[0]), "r"(a[1]), "r"(a[2]), "r"(a[3]), "r"(b0), "r"(b1));
}

#define CPA16(dst, src) \
    asm volatile("cp.async.cg.shared.global [%0], [%1], 16;" \
                 :: "r"(dst), "l"(src) : "memory")
#define CPA_COMMIT() asm volatile("cp.async.commit_group;" ::: "memory")
#define CPA_WAIT0()  asm volatile("cp.async.wait_group 0;" ::: "memory")

__device__ __forceinline__ uint32_t pack2(__nv_bfloat16 a, __nv_bfloat16 b) {
    __nv_bfloat162 t(a, b);
    return *(uint32_t*)&t;
}

__device__ __forceinline__ void split4(float4 v, uint2& hi, uint2& lo) {
    __nv_bfloat16 hx = __float2bfloat16(v.x), hy = __float2bfloat16(v.y);
    __nv_bfloat16 hz = __float2bfloat16(v.z), hw = __float2bfloat16(v.w);
    hi.x = pack2(hx, hy);
    hi.y = pack2(hz, hw);
    lo.x = pack2(__float2bfloat16(v.x - __bfloat162float(hx)),
                 __float2bfloat16(v.y - __bfloat162float(hy)));
    lo.y = pack2(__float2bfloat16(v.z - __bfloat162float(hz)),
                 __float2bfloat16(v.w - __bfloat162float(hw)));
}

// split a float pair into hi/lo packed words
__device__ __forceinline__ void split2(float a, float b, uint32_t& hi, uint32_t& lo) {
    __nv_bfloat16 ha = __float2bfloat16(a), hb = __float2bfloat16(b);
    hi = pack2(ha, hb);
    lo = pack2(__float2bfloat16(a - __bfloat162float(ha)),
               __float2bfloat16(b - __bfloat162float(hb)));
}

// ---------------------------------------------------------------------------
__global__ __launch_bounds__(256) void prep_qkv_kernel(
    const float* __restrict__ Q, const float* __restrict__ K,
    const float* __restrict__ V)
{
    size_t i4 = ((size_t)blockIdx.x * 256 + threadIdx.x) * 4;
    if (i4 >= NQK) return;
    uint2 hi, lo;
    split4(*(const float4*)&Q[i4], hi, lo);
    *(uint2*)&g_qh[i4] = hi;
    *(uint2*)&g_ql[i4] = lo;
    split4(*(const float4*)&K[i4], hi, lo);
    *(uint2*)&g_kh[i4] = hi;
    *(uint2*)&g_kl[i4] = lo;
    split4(*(const float4*)&V[i4], hi, lo);
    *(uint2*)&g_vh[i4] = hi;
    *(uint2*)&g_vl[i4] = lo;
}

// ---------------------------------------------------------------------------
__global__ __launch_bounds__(256) void prep_mask_kernel(const void* __restrict__ m)
{
    const int flag = g_mask_flag;
    size_t w32 = (size_t)blockIdx.x * 256 + threadIdx.x;
    if (w32 >= (size_t)BB * SS * SS / 32) return;
    size_t e0 = w32 * 32;
    uint32_t bits = 0;
    if (flag == 2) {
        const unsigned char* mp = (const unsigned char*)m + e0;
#pragma unroll
        for (int q = 0; q < 2; q++) {
            uint4 w = *(const uint4*)&mp[q * 16];
            uint32_t ws[4] = {w.x, w.y, w.z, w.w};
#pragma unroll
            for (int k = 0; k < 4; k++)
#pragma unroll
                for (int bidx = 0; bidx < 4; bidx++)
                    if ((ws[k] >> (bidx * 8)) & 0xFF)
                        bits |= 1u << (q * 16 + k * 4 + bidx);
        }
    } else {
        const int* mp = (const int*)m + e0;
#pragma unroll
        for (int q = 0; q < 8; q++) {
            int4 w = *(const int4*)&mp[q * 4];
            if (w.x) bits |= 1u << (q * 4);
            if (w.y) bits |= 1u << (q * 4 + 1);
            if (w.z) bits |= 1u << (q * 4 + 2);
            if (w.w) bits |= 1u << (q * 4 + 3);
        }
    }
    ((uint32_t*)g_maskbits)[w32] = bits;
}

// ---------------------------------------------------------------------------
// FUSED recompute attention. CTA = 128-q strip, 8 warps x 16 rows each.
// Pass A: single-term bf16 QK over 32 chunks of 64k; row sums in registers.
// Pass B: 3-term QK, p = e*sinv, write FINAL p once; P fragments packed
//   from accumulators (C->A layout identity) feed 3-term PV; ctx in regs.
// ---------------------------------------------------------------------------
__global__ __launch_bounds__(256, 2) void fused_attn_kernel(
    float* __restrict__ attn, float* __restrict__ ctx)
{
    extern __shared__ __align__(16) char smem[];
    __nv_bfloat16* Qh = (__nv_bfloat16*)smem;
    __nv_bfloat16* Ql = (__nv_bfloat16*)(smem + QPLN);

    const int tid = threadIdx.x, lane = tid & 31, wid = tid >> 5;
    const int bh = blockIdx.y, b = bh >> 4;
    const int q0 = blockIdx.x * 128;
    const int m0 = wid * 16;
    const int rr = lane >> 2, cc = (lane & 3) * 2;
    const int arow = lane & 15, acol8 = (lane >> 4) * 8;

    const size_t qoff = ((size_t)bh * SS + q0) * DD;
    const size_t koff = (size_t)bh * SS * DD;
    const uint32_t kbU = smem_u32(smem + KB_OFF);
    const uint32_t vbU = smem_u32(smem + VB_OFF);
    const uint32_t QhU = smem_u32(Qh), QlU = smem_u32(Ql);

    // cp.async slots: 64x64 bf16 plane = 512 uint4; 2 per thread
    int krow[2], kcol[2];
#pragma unroll
    for (int p = 0; p < 2; p++) {
        int i8 = tid + p * 256;
        krow[p] = i8 >> 3;
        kcol[p] = (i8 & 7) * 8;
    }

    const unsigned char* mb = (const unsigned char*)g_maskbits
        + ((size_t)b * SS + q0 + m0 + rr) * MROWB;

    // ====================== PASS A: row sums =================================
    // prefetch Kh(0) -> buf0
#pragma unroll
    for (int p = 0; p < 2; p++) {
        uint32_t off = (uint32_t)((krow[p] * PADA + kcol[p]) * 2);
        CPA16(kbU + off, &g_kh[koff + krow[p] * DD + kcol[p]]);
    }
    CPA_COMMIT();

    // Q -> smem (both planes), overlaps K(0)
    for (int i8 = tid; i8 < 128 * 8; i8 += 256) {
        int r = i8 >> 3, c8 = (i8 & 7) * 8;
        *(uint4*)&Qh[r * PADA + c8] = *(const uint4*)&g_qh[qoff + r * DD + c8];
        *(uint4*)&Ql[r * PADA + c8] = *(const uint4*)&g_ql[qoff + r * DD + c8];
    }

    uint32_t ma0, ma1, mb0, mb1;
    {
        uint2 a = *(const uint2*)mb;
        uint2 c = *(const uint2*)(mb + 8 * MROWB);
        ma0 = a.x >> cc; ma1 = a.y >> cc;
        mb0 = c.x >> cc; mb1 = c.y >> cc;
    }

    CPA_WAIT0();
    __syncthreads();

    float srow0 = 0.0f, srow1 = 0.0f;

    for (int c = 0; c < 32; c++) {
        const int cur = c & 1;
        uint32_t na0 = 0, na1 = 0, nb0 = 0, nb1 = 0;
        if (c < 31) {
            const size_t ko2 = koff + (size_t)(c + 1) * 64 * DD;
            const uint32_t dst = kbU + (uint32_t)((1 - cur) * 2 * PLN64);
#pragma unroll
            for (int p = 0; p < 2; p++) {
                uint32_t off = (uint32_t)((krow[p] * PADA + kcol[p]) * 2);
                CPA16(dst + off, &g_kh[ko2 + krow[p] * DD + kcol[p]]);
            }
            CPA_COMMIT();
            uint2 a = *(const uint2*)(mb + (c + 1) * 8);
            uint2 d = *(const uint2*)(mb + (c + 1) * 8 + 8 * MROWB);
            na0 = a.x >> cc; na1 = a.y >> cc;
            nb0 = d.x >> cc; nb1 = d.y >> cc;
        }

        float acc[8][4];
#pragma unroll
        for (int j = 0; j < 8; j++)
#pragma unroll
            for (int v = 0; v < 4; v++) acc[j][v] = 0.0f;

        const uint32_t KhU = kbU + (uint32_t)(cur * 2 * PLN64);
#pragma unroll
        for (int ks = 0; ks < 4; ks++) {
            const int k = ks * 16;
            uint32_t aQ[4];
            ldsm4(aQ, QhU + (uint32_t)(((m0 + arow) * PADA + k + acol8) * 2));
#pragma unroll
            for (int jj = 0; jj < 4; jj++) {
                uint32_t bK[4];
                ldsm4(bK, KhU + (uint32_t)(((jj * 16 + arow) * PADA + k + acol8) * 2));
                mma_bf16(acc[2 * jj],     aQ, bK[0], bK[2]);
                mma_bf16(acc[2 * jj + 1], aQ, bK[1], bK[3]);
            }
        }

#pragma unroll
        for (int j = 0; j < 8; j++) {
            uint32_t wa = (j < 4) ? ma0 : ma1;
            uint32_t wb = (j < 4) ? mb0 : mb1;
            const int sh = (j & 3) * 8;
            srow0 += (((wa >> sh) & 1u)       ? 0.0f : exp2f(acc[j][0] * SCL2E))
                   + (((wa >> (sh + 1)) & 1u) ? 0.0f : exp2f(acc[j][1] * SCL2E));
            srow1 += (((wb >> sh) & 1u)       ? 0.0f : exp2f(acc[j][2] * SCL2E))
                   + (((wb >> (sh + 1)) & 1u) ? 0.0f : exp2f(acc[j][3] * SCL2E));
        }

        if (c < 31) CPA_WAIT0();
        __syncthreads();
        ma0 = na0; ma1 = na1; mb0 = nb0; mb1 = nb1;
    }

    // rows owned entirely by this warp: quad reduce only
    srow0 += __shfl_xor_sync(0xffffffffu, srow0, 1);
    srow0 += __shfl_xor_sync(0xffffffffu, srow0, 2);
    srow1 += __shfl_xor_sync(0xffffffffu, srow1, 1);
    srow1 += __shfl_xor_sync(0xffffffffu, srow1, 2);
    const float sinv0 = 1.0f / srow0;
    const float sinv1 = 1.0f / srow1;

    // ====================== PASS B: p + ctx ==================================
    // prefetch K(0) hi/lo and V(0) hi/lo
    {
        const size_t vo = (size_t)bh * SS * DD;
#pragma unroll
        for (int p = 0; p < 2; p++) {
            uint32_t off = (uint32_t)((krow[p] * PADA + kcol[p]) * 2);
            CPA16(kbU + off,          &g_kh[koff + krow[p] * DD + kcol[p]]);
            CPA16(kbU + PLN64 + off,  &g_kl[koff + krow[p] * DD + kcol[p]]);
            CPA16(vbU + off,          &g_vh[vo + krow[p] * DD + kcol[p]]);
            CPA16(vbU + PLN64 + off,  &g_vl[vo + krow[p] * DD + kcol[p]]);
        }
        CPA_COMMIT();
        uint2 a = *(const uint2*)mb;
        uint2 d = *(const uint2*)(mb + 8 * MROWB);
        ma0 = a.x >> cc; ma1 = a.y >> cc;
        mb0 = d.x >> cc; mb1 = d.y >> cc;
    }
    CPA_WAIT0();
    __syncthreads();

    float cacc[8][4];
#pragma unroll
    for (int j = 0; j < 8; j++)
#pragma unroll
        for (int v = 0; v < 4; v++) cacc[j][v] = 0.0f;

    for (int c = 0; c < 32; c++) {
        const int cur = c & 1;
        uint32_t na0 = 0, na1 = 0, nb0 = 0, nb1 = 0;
        if (c < 31) {
            const size_t ko2 = koff + (size_t)(c + 1) * 64 * DD;
            const uint32_t kd = kbU + (uint32_t)((1 - cur) * 2 * PLN64);
            const uint32_t vd = vbU + (uint32_t)((1 - cur) * 2 * PLN64);
#pragma unroll
            for (int p = 0; p < 2; p++) {
                uint32_t off = (uint32_t)((krow[p] * PADA + kcol[p]) * 2);
                CPA16(kd + off,         &g_kh[ko2 + krow[p] * DD + kcol[p]]);
                CPA16(kd + PLN64 + off, &g_kl[ko2 + krow[p] * DD + kcol[p]]);
                CPA16(vd + off,         &g_vh[ko2 + krow[p] * DD + kcol[p]]);
                CPA16(vd + PLN64 + off, &g_vl[ko2 + krow[p] * DD + kcol[p]]);
            }
            CPA_COMMIT();
            uint2 a = *(const uint2*)(mb + (c + 1) * 8);
            uint2 d = *(const uint2*)(mb + (c + 1) * 8 + 8 * MROWB);
            na0 = a.x >> cc; na1 = a.y >> cc;
            nb0 = d.x >> cc; nb1 = d.y >> cc;
        }

        // 3-term QK
        float acc[8][4];
#pragma unroll
        for (int j = 0; j < 8; j++)
#pragma unroll
            for (int v = 0; v < 4; v++) acc[j][v] = 0.0f;

        const uint32_t KhU = kbU + (uint32_t)(cur * 2 * PLN64);
        const uint32_t KlU = KhU + PLN64;
#pragma unroll
        for (int ks = 0; ks < 4; ks++) {
            const int k = ks * 16;
            uint32_t aQh[4], aQl[4];
            ldsm4(aQh, QhU + (uint32_t)(((m0 + arow) * PADA + k + acol8) * 2));
            ldsm4(aQl, QlU + (uint32_t)(((m0 + arow) * PADA + k + acol8) * 2));
#pragma unroll
            for (int jj = 0; jj < 4; jj++) {
                uint32_t bKh[4], bKl[4];
                uint32_t boff = (uint32_t)(((jj * 16 + arow) * PADA + k + acol8) * 2);
                ldsm4(bKh, KhU + boff);
                ldsm4(bKl, KlU + boff);
                mma_bf16(acc[2 * jj],     aQh, bKh[0], bKh[2]);
                mma_bf16(acc[2 * jj + 1], aQh, bKh[1], bKh[3]);
                mma_bf16(acc[2 * jj],     aQh, bKl[0], bKl[2]);
                mma_bf16(acc[2 * jj + 1], aQh, bKl[1], bKl[3]);
                mma_bf16(acc[2 * jj],     aQl, bKh[0], bKh[2]);
                mma_bf16(acc[2 * jj + 1], aQl, bKh[1], bKh[3]);
            }
        }

        // p = e*sinv; store final p; pack A-fragments (hi/lo)
        uint32_t Ph[4][4], Pl[4][4];
        size_t abase = ((size_t)bh * SS + q0 + m0 + rr) * SS + (size_t)c * 64 + cc;
#pragma unroll
        for (int j = 0; j < 8; j++) {
            uint32_t wa = (j < 4) ? ma0 : ma1;
            uint32_t wb = (j < 4) ? mb0 : mb1;
            const int sh = (j & 3) * 8;
            float p0 = (((wa >> sh) & 1u)       ? 0.0f : exp2f(acc[j][0] * SCL2E)) * sinv0;
            float p1 = (((wa >> (sh + 1)) & 1u) ? 0.0f : exp2f(acc[j][1] * SCL2E)) * sinv0;
            float p2 = (((wb >> sh) & 1u)       ? 0.0f : exp2f(acc[j][2] * SCL2E)) * sinv1;
            float p3 = (((wb >> (sh + 1)) & 1u) ? 0.0f : exp2f(acc[j][3] * SCL2E)) * sinv1;
            *(float2*)&attn[abase + j * 8]          = make_float2(p0, p1);
            *(float2*)&attn[abase + j * 8 + 8 * SS] = make_float2(p2, p3);
            const int ksB = j >> 1;
            const int half = (j & 1) * 2;   // 0 -> a0,a1 ; 1 -> a2,a3
            split2(p0, p1, Ph[ksB][half],     Pl[ksB][half]);
            split2(p2, p3, Ph[ksB][half + 1], Pl[ksB][half + 1]);
        }

        // PV: ctx += P x V  (3 terms: PhVh, PlVh, PhVl)
        const uint32_t VhU = vbU + (uint32_t)(cur * 2 * PLN64);
        const uint32_t VlU = VhU + PLN64;
#pragma unroll
        for (int ks = 0; ks < 4; ks++) {
            const int kk = ks * 16;
#pragma unroll
            for (int w = 0; w < 4; w++) {
                uint32_t bt[4];
                ldsm4t(bt, VhU + (uint32_t)(((kk + arow) * PADA + w * 16 + acol8) * 2));
                mma_bf16(cacc[2 * w],     Ph[ks], bt[0], bt[1]);
                mma_bf16(cacc[2 * w + 1], Ph[ks], bt[2], bt[3]);
                mma_bf16(cacc[2 * w],     Pl[ks], bt[0], bt[1]);
                mma_bf16(cacc[2 * w + 1], Pl[ks], bt[2], bt[3]);
            }
#pragma unroll
            for (int w = 0; w < 4; w++) {
                uint32_t bt[4];
                ldsm4t(bt, VlU + (uint32_t)(((kk + arow) * PADA + w * 16 + acol8) * 2));
                mma_bf16(cacc[2 * w],     Ph[ks], bt[0], bt[1]);
                mma_bf16(cacc[2 * w + 1], Ph[ks], bt[2], bt[3]);
            }
        }

        if (c < 31) CPA_WAIT0();
        __syncthreads();
        ma0 = na0; ma1 = na1; mb0 = nb0; mb1 = nb1;
    }

    // ctx epilogue (rows m0+rr, m0+rr+8; cols j*8+cc)
    float* cb = ctx + ((size_t)bh * SS + q0 + m0 + rr) * DD + cc;
#pragma unroll
    for (int j = 0; j < 8; j++) {
        *(float2*)&cb[j * 8]          = make_float2(cacc[j][0], cacc[j][1]);
        *(float2*)&cb[j * 8 + 8 * DD] = make_float2(cacc[j][2], cacc[j][3]);
    }
}

// ---------------------------------------------------------------------------
extern "C" void kernel_launch(void* const* d_in, const int* in_sizes, int n_in,
                              void* d_out, int out_size)
{
    const float* Q = (const float*)d_in[0];
    const float* K = (const float*)d_in[1];
    const float* V = (const float*)d_in[2];
    const void*  M = d_in[3];

    float* out  = (float*)d_out;
    float* ctx  = out;
    float* attn = out + NQK;

    cudaFuncSetAttribute(fused_attn_kernel,
                         cudaFuncAttributeMaxDynamicSharedMemorySize, FUSED_SMEM);

    probe_mask_kernel<<<1, 256>>>(M);
    prep_mask_kernel<<<(unsigned)((size_t)BB * SS * SS / 32 / 256), 256>>>(M);
    prep_qkv_kernel<<<(unsigned)((NQK / 4 + 255) / 256), 256>>>(Q, K, V);

    dim3 g(SS / 128, BB * HH);
    fused_attn_kernel<<<g, 256, FUSED_SMEM>>>(attn, ctx);
}

// round 16
// speedup vs baseline: 1.1510x; 1.1510x over previous
#include <cuda_runtime.h>
#include <cuda_bf16.h>
#include <cuda_fp16.h>
#include <cstdint>

#define BB 2
#define HH 16
#define SS 2048
#define DD 64
#define SCL2E 0.1803368801111243f   /* (1/8) * log2(e) */
#define PADA 72
#define NQT 16
#define PLN64 (64 * PADA * 2)       /* 9216 */
#define NQK ((size_t)BB * HH * SS * DD)
#define MROWB (SS / 8)
#define QPLN (64 * PADA * 2)        /* 9216 */
#define KPLN (128 * PADA * 2)       /* 18432 */
#define WREDS_OFF (2 * QPLN + 4 * KPLN)   /* 92160 */
#define SINV_OFF  (WREDS_OFF + 512)
#define FUSED_SMEM (SINV_OFF + 256)       /* 92928 */

__device__ int g_mask_flag;
__device__ __nv_bfloat16 g_qh[NQK], g_ql[NQK], g_kh[NQK], g_kl[NQK];
__device__ __half g_vh[NQK], g_vl[NQK];
__device__ unsigned long long g_maskbits[(size_t)BB * SS * SS / 64];

// ---------------------------------------------------------------------------
__global__ void probe_mask_kernel(const void* m) {
    uint4 w = ((const uint4*)m)[threadIdx.x];
    bool a01 = (w.x <= 1u) && (w.y <= 1u) && (w.z <= 1u) && (w.w <= 1u);
    auto okf = [](unsigned v) { return v == 0u || v == 0x3F800000u; };
    bool af = okf(w.x) && okf(w.y) && okf(w.z) && okf(w.w);
    int all1 = __syncthreads_and((int)a01);
    int all2 = __syncthreads_and((int)af);
    if (threadIdx.x == 0) g_mask_flag = all1 ? 0 : (all2 ? 1 : 2);
}

// ---------------------------------------------------------------------------
__device__ __forceinline__ uint32_t smem_u32(const void* p) {
    uint32_t a;
    asm("{ .reg .u64 t; cvta.to.shared.u64 t, %1; cvt.u32.u64 %0, t; }"
        : "=r"(a) : "l"(p));
    return a;
}

__device__ __forceinline__ void ldsm4(uint32_t* r, uint32_t addr) {
    asm volatile("ldmatrix.sync.aligned.m8n8.x4.shared.b16 {%0,%1,%2,%3}, [%4];"
                 : "=r"(r[0]), "=r"(r[1]), "=r"(r[2]), "=r"(r[3]) : "r"(addr));
}

__device__ __forceinline__ void ldsm4t(uint32_t* r, uint32_t addr) {
    asm volatile("ldmatrix.sync.aligned.m8n8.x4.trans.shared.b16 {%0,%1,%2,%3}, [%4];"
                 : "=r"(r[0]), "=r"(r[1]), "=r"(r[2]), "=r"(r[3]) : "r"(addr));
}

__device__ __forceinline__ void mma_bf16(float* c, const uint32_t* a,
                                         const uint32_t b0, const uint32_t b1) {
    asm volatile(
        "mma.sync.aligned.m16n8k16.row.col.f32.bf16.bf16.f32 "
        "{%0,%1,%2,%3}, {%4,%5,%6,%7}, {%8,%9}, {%0,%1,%2,%3};"
        : "+f"(c[0]), "+f"(c[1]), "+f"(c[2]), "+f"(c[3])
        : "r"(a[0]), "r"(a[1]), "r"(a[2]), "r"(a[3]), "r"(b0), "r"(b1));
}

__device__ __forceinline__ void mma_fp16(float* c, const uint32_t* a,
                                         const uint32_t b0, const uint32_t b1) {
    asm volatile(
        "mma.sync.aligned.m16n8k16.row.col.f32.f16.f16.f32 "
        "{%0,%1,%2,%3}, {%4,%5,%6,%7}, {%8,%9}, {%0,%1,%2,%3};"
        : "+f"(c[0]), "+f"(c[1]), "+f"(c[2]), "+f"(c[3])
        : "r"(a[0]), "r"(a[1]), "r"(a[2]), "r"(a[3]), "r"(b0), "r"(b1));
}

#define CPA16(dst, src) \
    asm volatile("cp.async.cg.shared.global [%0], [%1], 16;" \
                 :: "r"(dst), "l"(src) : "memory")
#define CPA_COMMIT() asm volatile("cp.async.commit_group;" ::: "memory")
#define CPA_WAIT0()  asm volatile("cp.async.wait_group 0;" ::: "memory")

__device__ __forceinline__ uint32_t pack2(__nv_bfloat16 a, __nv_bfloat16 b) {
    __nv_bfloat162 t(a, b);
    return *(uint32_t*)&t;
}

__device__ __forceinline__ uint32_t packh2(__half a, __half b) {
    __half2 t(a, b);
    return *(uint32_t*)&t;
}

__device__ __forceinline__ void split4(float4 v, uint2& hi, uint2& lo) {
    __nv_bfloat16 hx = __float2bfloat16(v.x), hy = __float2bfloat16(v.y);
    __nv_bfloat16 hz = __float2bfloat16(v.z), hw = __float2bfloat16(v.w);
    hi.x = pack2(hx, hy);
    hi.y = pack2(hz, hw);
    lo.x = pack2(__float2bfloat16(v.x - __bfloat162float(hx)),
                 __float2bfloat16(v.y - __bfloat162float(hy)));
    lo.y = pack2(__float2bfloat16(v.z - __bfloat162float(hz)),
                 __float2bfloat16(v.w - __bfloat162float(hw)));
}

__device__ __forceinline__ void splith4(float4 v, uint2& hi, uint2& lo) {
    __half hx = __float2half_rn(v.x), hy = __float2half_rn(v.y);
    __half hz = __float2half_rn(v.z), hw = __float2half_rn(v.w);
    hi.x = packh2(hx, hy);
    hi.y = packh2(hz, hw);
    lo.x = packh2(__float2half_rn(v.x - __half2float(hx)),
                  __float2half_rn(v.y - __half2float(hy)));
    lo.y = packh2(__float2half_rn(v.z - __half2float(hz)),
                  __float2half_rn(v.w - __half2float(hw)));
}

// ---------------------------------------------------------------------------
__global__ __launch_bounds__(256) void prep_qkv_kernel(
    const float* __restrict__ Q, const float* __restrict__ K,
    const float* __restrict__ V)
{
    size_t i4 = ((size_t)blockIdx.x * 256 + threadIdx.x) * 4;
    if (i4 >= NQK) return;
    uint2 hi, lo;
    split4(*(const float4*)&Q[i4], hi, lo);
    *(uint2*)&g_qh[i4] = hi;
    *(uint2*)&g_ql[i4] = lo;
    split4(*(const float4*)&K[i4], hi, lo);
    *(uint2*)&g_kh[i4] = hi;
    *(uint2*)&g_kl[i4] = lo;
    splith4(*(const float4*)&V[i4], hi, lo);
    *(uint2*)&g_vh[i4] = hi;
    *(uint2*)&g_vl[i4] = lo;
}

// ---------------------------------------------------------------------------
__global__ __launch_bounds__(256) void prep_mask_kernel(const void* __restrict__ m)
{
    const int flag = g_mask_flag;
    size_t w32 = (size_t)blockIdx.x * 256 + threadIdx.x;
    if (w32 >= (size_t)BB * SS * SS / 32) return;
    size_t e0 = w32 * 32;
    uint32_t bits = 0;
    if (flag == 2) {
        const unsigned char* mp = (const unsigned char*)m + e0;
#pragma unroll
        for (int q = 0; q < 2; q++) {
            uint4 w = *(const uint4*)&mp[q * 16];
            uint32_t ws[4] = {w.x, w.y, w.z, w.w};
#pragma unroll
            for (int k = 0; k < 4; k++)
#pragma unroll
                for (int bidx = 0; bidx < 4; bidx++)
                    if ((ws[k] >> (bidx * 8)) & 0xFF)
                        bits |= 1u << (q * 16 + k * 4 + bidx);
        }
    } else {
        const int* mp = (const int*)m + e0;
#pragma unroll
        for (int q = 0; q < 8; q++) {
            int4 w = *(const int4*)&mp[q * 4];
            if (w.x) bits |= 1u << (q * 4);
            if (w.y) bits |= 1u << (q * 4 + 1);
            if (w.z) bits |= 1u << (q * 4 + 2);
            if (w.w) bits |= 1u << (q * 4 + 3);
        }
    }
    ((uint32_t*)g_maskbits)[w32] = bits;
}

// ---------------------------------------------------------------------------
// FUSED attention. CTA = 64-q strip.
// Phase 1 (QK, 3-term bf16): e -> attn, row sums -> sinv (smem).
// Phase 2 (PV, 2-term fp16): p = e*sinv written once; ctx += P(f16) x V(h+l).
// ---------------------------------------------------------------------------
__global__ __launch_bounds__(256, 2) void fused_attn_kernel(
    float* __restrict__ attn, float* __restrict__ ctx)
{
    extern __shared__ __align__(16) char smem[];
    float* wreds  = (float*)(smem + WREDS_OFF);
    float* sinv_s = (float*)(smem + SINV_OFF);

    const int tid = threadIdx.x, lane = tid & 31, wid = tid >> 5;
    const int bh = blockIdx.y, b = bh >> 4;
    const int q0 = blockIdx.x * 64;
    const int rr = lane >> 2, cc = (lane & 3) * 2;
    const int arow = lane & 15, acol8 = (lane >> 4) * 8;

    // =========================== PHASE 1: QK (unchanged) ====================
    {
        __nv_bfloat16* Qh = (__nv_bfloat16*)smem;
        __nv_bfloat16* Ql = (__nv_bfloat16*)(smem + QPLN);
        char* kbufs = smem + 2 * QPLN;
        const int wm = wid >> 1, wn = wid & 1;
        const int m0 = wm * 16, n0 = wn * 64;

        const size_t qoff = ((size_t)bh * SS + q0) * DD;
        const size_t koff = (size_t)bh * SS * DD;
        const uint32_t kbU = smem_u32(kbufs);

        int krow[4], kcol[4];
#pragma unroll
        for (int p = 0; p < 4; p++) {
            int i8 = tid + p * 256;
            krow[p] = i8 >> 3;
            kcol[p] = (i8 & 7) * 8;
        }

#pragma unroll
        for (int p = 0; p < 4; p++) {
            uint32_t off = (uint32_t)((krow[p] * PADA + kcol[p]) * 2);
            CPA16(kbU + off,        &g_kh[koff + krow[p] * DD + kcol[p]]);
            CPA16(kbU + KPLN + off, &g_kl[koff + krow[p] * DD + kcol[p]]);
        }
        CPA_COMMIT();

        for (int i8 = tid; i8 < 64 * 8; i8 += 256) {
            int r = i8 >> 3, c8 = (i8 & 7) * 8;
            *(uint4*)&Qh[r * PADA + c8] = *(const uint4*)&g_qh[qoff + r * DD + c8];
            *(uint4*)&Ql[r * PADA + c8] = *(const uint4*)&g_ql[qoff + r * DD + c8];
        }

        const unsigned char* mb = (const unsigned char*)g_maskbits
            + ((size_t)b * SS + q0 + m0 + rr) * MROWB + (n0 >> 3);
        uint32_t m00, m01, m10, m11;
        {
            uint2 a = *(const uint2*)mb;
            uint2 c = *(const uint2*)(mb + 8 * MROWB);
            m00 = a.x >> cc; m01 = a.y >> cc;
            m10 = c.x >> cc; m11 = c.y >> cc;
        }

        CPA_WAIT0();
        __syncthreads();

        const uint32_t QhU = smem_u32(Qh), QlU = smem_u32(Ql);
        float srow0 = 0.0f, srow1 = 0.0f;

        for (int kt = 0; kt < NQT; kt++) {
            const int cur = kt & 1;

            uint32_t n00 = 0, n01 = 0, n10 = 0, n11 = 0;
            if (kt < NQT - 1) {
                const size_t koff2 = koff + (size_t)(kt + 1) * 128 * DD;
                const uint32_t dst = kbU + (uint32_t)((1 - cur) * 2 * KPLN);
#pragma unroll
                for (int p = 0; p < 4; p++) {
                    uint32_t off = (uint32_t)((krow[p] * PADA + kcol[p]) * 2);
                    CPA16(dst + off,        &g_kh[koff2 + krow[p] * DD + kcol[p]]);
                    CPA16(dst + KPLN + off, &g_kl[koff2 + krow[p] * DD + kcol[p]]);
                }
                CPA_COMMIT();
                uint2 a = *(const uint2*)(mb + (kt + 1) * 16);
                uint2 c = *(const uint2*)(mb + (kt + 1) * 16 + 8 * MROWB);
                n00 = a.x >> cc; n01 = a.y >> cc;
                n10 = c.x >> cc; n11 = c.y >> cc;
            }

            float acc[8][4];
#pragma unroll
            for (int j = 0; j < 8; j++)
#pragma unroll
                for (int v = 0; v < 4; v++) acc[j][v] = 0.0f;

            const uint32_t KhU = kbU + (uint32_t)(cur * 2 * KPLN);
            const uint32_t KlU = KhU + KPLN;
#pragma unroll
            for (int ks = 0; ks < 4; ks++) {
                const int k = ks * 16;
                uint32_t aQh[4], aQl[4];
                ldsm4(aQh, QhU + (uint32_t)(((m0 + arow) * PADA + k + acol8) * 2));
                ldsm4(aQl, QlU + (uint32_t)(((m0 + arow) * PADA + k + acol8) * 2));
                uint32_t bKh[4][4], bKl[4][4];
#pragma unroll
                for (int jj = 0; jj < 4; jj++) {
                    uint32_t boff = (uint32_t)(((n0 + jj * 16 + arow) * PADA
                                                + k + acol8) * 2);
                    ldsm4(bKh[jj], KhU + boff);
                    ldsm4(bKl[jj], KlU + boff);
                }
#pragma unroll
                for (int jj = 0; jj < 4; jj++) {
                    mma_bf16(acc[2 * jj],     aQh, bKh[jj][0], bKh[jj][2]);
                    mma_bf16(acc[2 * jj + 1], aQh, bKh[jj][1], bKh[jj][3]);
                    mma_bf16(acc[2 * jj],     aQh, bKl[jj][0], bKl[jj][2]);
                    mma_bf16(acc[2 * jj + 1], aQh, bKl[jj][1], bKl[jj][3]);
                    mma_bf16(acc[2 * jj],     aQl, bKh[jj][0], bKh[jj][2]);
                    mma_bf16(acc[2 * jj + 1], aQl, bKh[jj][1], bKh[jj][3]);
                }
            }

            size_t abase = ((size_t)bh * SS + q0 + m0 + rr) * SS
                           + (size_t)kt * 128 + n0 + cc;
#pragma unroll
            for (int j = 0; j < 8; j++) {
                uint32_t wa = (j < 4) ? m00 : m01;
                uint32_t wb = (j < 4) ? m10 : m11;
                const int sh = (j & 3) * 8;
                float e0 = ((wa >> sh) & 1u)       ? 0.0f : exp2f(acc[j][0] * SCL2E);
                float e1 = ((wa >> (sh + 1)) & 1u) ? 0.0f : exp2f(acc[j][1] * SCL2E);
                float f0 = ((wb >> sh) & 1u)       ? 0.0f : exp2f(acc[j][2] * SCL2E);
                float f1 = ((wb >> (sh + 1)) & 1u) ? 0.0f : exp2f(acc[j][3] * SCL2E);
                srow0 += e0 + e1;
                srow1 += f0 + f1;
                *(float2*)&attn[abase + j * 8]          = make_float2(e0, e1);
                *(float2*)&attn[abase + j * 8 + 8 * SS] = make_float2(f0, f1);
            }

            if (kt < NQT - 1) CPA_WAIT0();
            __syncthreads();
            m00 = n00; m01 = n01; m10 = n10; m11 = n11;
        }

        srow0 += __shfl_xor_sync(0xffffffffu, srow0, 1);
        srow0 += __shfl_xor_sync(0xffffffffu, srow0, 2);
        srow1 += __shfl_xor_sync(0xffffffffu, srow1, 1);
        srow1 += __shfl_xor_sync(0xffffffffu, srow1, 2);
        if ((lane & 3) == 0) {
            wreds[wn * 64 + m0 + rr]     = srow0;
            wreds[wn * 64 + m0 + 8 + rr] = srow1;
        }
        __syncthreads();
        if (tid < 64)
            sinv_s[tid] = 1.0f / (wreds[tid] + wreds[64 + tid]);
        __syncthreads();
    }

    // =========================== PHASE 2: PV (fp16, 2-term) =================
    {
        float* Ap = attn + ((size_t)bh * SS + q0) * SS;
        const size_t vo = (size_t)bh * SS * DD;

        int lr[4], lc[4];
#pragma unroll
        for (int t = 0; t < 4; t++) {
            int i4 = tid + t * 256;
            lr[t] = i4 >> 4;
            lc[t] = (i4 & 15) * 4;
        }
        int vrow[2], vcol[2];
#pragma unroll
        for (int p = 0; p < 2; p++) {
            int i8 = tid + p * 256;
            vrow[p] = i8 >> 3;
            vcol[p] = (i8 & 7) * 8;
        }

        const uint32_t sbU = smem_u32(smem);
        const int wm = wid >> 1, wn = wid & 1;
        const int m0 = wm * 16, n0 = wn * 32;

        float acc[4][4];
#pragma unroll
        for (int j = 0; j < 4; j++)
#pragma unroll
            for (int v = 0; v < 4; v++) acc[j][v] = 0.0f;

        // prologue: V(0) via cp.async; P(0) via registers
#pragma unroll
        for (int p = 0; p < 2; p++) {
            uint32_t off = (uint32_t)((vrow[p] * PADA + vcol[p]) * 2);
            CPA16(sbU + PLN64 + off,     &g_vh[vo + vrow[p] * DD + vcol[p]]);
            CPA16(sbU + 2 * PLN64 + off, &g_vl[vo + vrow[p] * DD + vcol[p]]);
        }
        CPA_COMMIT();

        float4 pr[4];
#pragma unroll
        for (int t = 0; t < 4; t++)
            pr[t] = *(const float4*)&Ap[(size_t)lr[t] * SS + lc[t]];
#pragma unroll
        for (int t = 0; t < 4; t++) {
            float iv = sinv_s[lr[t]];
            float4 p = make_float4(pr[t].x * iv, pr[t].y * iv,
                                   pr[t].z * iv, pr[t].w * iv);
            *(float4*)&Ap[(size_t)lr[t] * SS + lc[t]] = p;
            uint2 h;
            h.x = packh2(__float2half_rn(p.x), __float2half_rn(p.y));
            h.y = packh2(__float2half_rn(p.z), __float2half_rn(p.w));
            *(uint2*)(smem + (lr[t] * PADA + lc[t]) * 2) = h;
        }
        CPA_WAIT0();
        __syncthreads();

        for (int kc = 0; kc < 32; kc++) {
            const int cur = kc & 1;
            if (kc < 31) {
                const int kn = (kc + 1) * 64;
                const uint32_t dst = sbU + (uint32_t)((1 - cur) * 3 * PLN64);
#pragma unroll
                for (int p = 0; p < 2; p++) {
                    uint32_t off = (uint32_t)((vrow[p] * PADA + vcol[p]) * 2);
                    CPA16(dst + PLN64 + off,
                          &g_vh[vo + (size_t)(kn + vrow[p]) * DD + vcol[p]]);
                    CPA16(dst + 2 * PLN64 + off,
                          &g_vl[vo + (size_t)(kn + vrow[p]) * DD + vcol[p]]);
                }
                CPA_COMMIT();
#pragma unroll
                for (int t = 0; t < 4; t++)
                    pr[t] = *(const float4*)&Ap[(size_t)lr[t] * SS + kn + lc[t]];
            }

            const uint32_t bufU = sbU + (uint32_t)(cur * 3 * PLN64);
            const uint32_t PU = bufU, VhU = bufU + PLN64, VlU = bufU + 2 * PLN64;
#pragma unroll
            for (int ks = 0; ks < 4; ks++) {
                const int kk = ks * 16;
                uint32_t a[4];
                ldsm4(a, PU + (uint32_t)(((m0 + arow) * PADA + kk + acol8) * 2));
                uint32_t bh0[4], bh1[4];
                ldsm4t(bh0, VhU + (uint32_t)(((kk + arow) * PADA + n0 + acol8) * 2));
                ldsm4t(bh1, VhU + (uint32_t)(((kk + arow) * PADA + n0 + 16 + acol8) * 2));
                mma_fp16(acc[0], a, bh0[0], bh0[1]);
                mma_fp16(acc[1], a, bh0[2], bh0[3]);
                mma_fp16(acc[2], a, bh1[0], bh1[1]);
                mma_fp16(acc[3], a, bh1[2], bh1[3]);
                uint32_t bl0[4], bl1[4];
                ldsm4t(bl0, VlU + (uint32_t)(((kk + arow) * PADA + n0 + acol8) * 2));
                ldsm4t(bl1, VlU + (uint32_t)(((kk + arow) * PADA + n0 + 16 + acol8) * 2));
                mma_fp16(acc[0], a, bl0[0], bl0[1]);
                mma_fp16(acc[1], a, bl0[2], bl0[3]);
                mma_fp16(acc[2], a, bl1[0], bl1[1]);
                mma_fp16(acc[3], a, bl1[2], bl1[3]);
            }

            if (kc < 31) {
                const int kn = (kc + 1) * 64;
                char* buf = (char*)smem + (1 - cur) * 3 * PLN64;
#pragma unroll
                for (int t = 0; t < 4; t++) {
                    float iv = sinv_s[lr[t]];
                    float4 p = make_float4(pr[t].x * iv, pr[t].y * iv,
                                           pr[t].z * iv, pr[t].w * iv);
                    *(float4*)&Ap[(size_t)lr[t] * SS + kn + lc[t]] = p;
                    uint2 h;
                    h.x = packh2(__float2half_rn(p.x), __float2half_rn(p.y));
                    h.y = packh2(__float2half_rn(p.z), __float2half_rn(p.w));
                    *(uint2*)(buf + (lr[t] * PADA + lc[t]) * 2) = h;
                }
                CPA_WAIT0();
            }
            __syncthreads();
        }

        const int row = q0 + m0 + rr;
        float* cb = ctx + ((size_t)bh * SS + row) * DD + n0 + cc;
#pragma unroll
        for (int j = 0; j < 4; j++) {
            *(float2*)&cb[j * 8]          = make_float2(acc[j][0], acc[j][1]);
            *(float2*)&cb[j * 8 + 8 * DD] = make_float2(acc[j][2], acc[j][3]);
        }
    }
}

// ---------------------------------------------------------------------------
extern "C" void kernel_launch(void* const* d_in, const int* in_sizes, int n_in,
                              void* d_out, int out_size)
{
    const float* Q = (const float*)d_in[0];
    const float* K = (const float*)d_in[1];
    const float* V = (const float*)d_in[2];
    const void*  M = d_in[3];

    float* out  = (float*)d_out;
    float* ctx  = out;
    float* attn = out + NQK;

    cudaFuncSetAttribute(fused_attn_kernel,
                         cudaFuncAttributeMaxDynamicSharedMemorySize, FUSED_SMEM);

    probe_mask_kernel<<<1, 256>>>(M);
    prep_mask_kernel<<<(unsigned)((size_t)BB * SS * SS / 32 / 256), 256>>>(M);
    prep_qkv_kernel<<<(unsigned)((NQK / 4 + 255) / 256), 256>>>(Q, K, V);

    dim3 g(SS / 64, BB * HH);
    fused_attn_kernel<<<g, 256, FUSED_SMEM>>>(attn, ctx);
}